// round 9
// baseline (speedup 1.0000x reference)
#include <cuda_runtime.h>
#include <cstdint>

#define BATCH 16
#define NPROP 2048
#define NCLS 80
#define NCLS1 81
#define KTOP 2048
#define CAP 16384
#define SCORE_THR 0.05f
#define IOU_THR 0.5f
#define MAXR 4.135166556742356f
#define OUTK 100
#define HISTN 3072
#define BINS 2304
#define SLOTS 4096
#define NT 1024

typedef unsigned long long ull;
typedef unsigned char uchar;

// ---------------- device scratch ----------------
__device__ ull g_keys[BATCH][CAP];
__device__ int g_cnt[BATCH];          // zero-init; re-zeroed in k_select
__device__ ull g_skey[BATCH][KTOP];
__device__ int g_valid[BATCH];
__device__ float4 g_obox[BATCH][KTOP];   // offset boxes (NMS space)
__device__ float4 g_bout[BATCH][KTOP];   // clipped boxes (output space)
__device__ uchar g_lab[BATCH][KTOP];
__device__ uchar g_alive[BATCH][KTOP];
__device__ int g_done[BATCH];            // zero-init; re-zeroed by emitting block

__device__ __forceinline__ int score_bin(unsigned u) {
    int bn = (int)(u >> 14) - 62770;
    return min(max(bn, 0), BINS - 1);
}

// ---------------- 1: softmax + threshold + block-aggregated compaction ----------------
__global__ void k_softmax_compact(const float* __restrict__ cls) {
    __shared__ int s_cnt, s_base;
    __shared__ ull s_buf[176];
    int tid = threadIdx.x;
    int lane = tid & 31;
    int w = tid >> 5;
    int gw = blockIdx.x * 8 + w;
    int b = gw >> 11;
    int n = gw & (NPROP - 1);

    if (tid == 0) s_cnt = 0;
    __syncthreads();

    const float* x = cls + (size_t)gw * NCLS1;
    float v0 = x[lane];
    float v1 = x[lane + 32];
    float v2 = (lane < 17) ? x[lane + 64] : -3.4e38f;
    float m = fmaxf(fmaxf(v0, v1), v2);
#pragma unroll
    for (int o = 16; o > 0; o >>= 1) m = fmaxf(m, __shfl_xor_sync(0xffffffffu, m, o));
    float e0 = expf(v0 - m);
    float e1 = expf(v1 - m);
    float e2 = (lane < 17) ? expf(v2 - m) : 0.0f;
    float s = e0 + e1 + e2;
#pragma unroll
    for (int o = 16; o > 0; o >>= 1) s += __shfl_xor_sync(0xffffffffu, s, o);

    auto push = [&](bool cond, float p, unsigned idx) {
        unsigned mask = __ballot_sync(0xffffffffu, cond);
        if (cond) {
            unsigned u = __float_as_uint(p);
            int leader = __ffs(mask) - 1;
            int base = 0;
            if (lane == leader) base = atomicAdd(&s_cnt, __popc(mask));
            base = __shfl_sync(mask, base, leader);
            s_buf[base + __popc(mask & ((1u << lane) - 1))] = ((ull)(~u) << 32) | idx;
        }
    };
    float p0 = e0 / s;
    push(p0 > SCORE_THR, p0, (unsigned)(n * NCLS + lane));
    float p1 = e1 / s;
    push(p1 > SCORE_THR, p1, (unsigned)(n * NCLS + lane + 32));
    float p2 = e2 / s;
    push((lane < 16) && (p2 > SCORE_THR), p2, (unsigned)(n * NCLS + lane + 64));
    __syncthreads();

    if (tid == 0) s_base = atomicAdd(&g_cnt[b], s_cnt);
    __syncthreads();
    int cnt = s_cnt, base = s_base;
    for (int i = tid; i < cnt; i += 256)
        if (base + i < CAP) g_keys[b][base + i] = s_buf[i];
}

// ---------------- 2: select (hist+scan+scatter) + fused rank-place/decode ----------------
// smem: tmpk 32768 | hist 12288 | base 12288 = 57344
#define SMEM_SEL 57344
extern __shared__ char dynsel[];

__global__ void __launch_bounds__(NT) k_select(const float* __restrict__ reg,
                                               const float* __restrict__ props,
                                               const int* __restrict__ hw) {
    int b = blockIdx.x;
    int tid = threadIdx.x;
    int lane = tid & 31;
    int warp = tid >> 5;

    ull* tmpk = (ull*)dynsel;
    int* hist = (int*)(dynsel + 32768);
    int* base = (int*)(dynsel + 45056);
    __shared__ int s_wsum[32];

    int cnt = min(g_cnt[b], CAP);

    for (int i = tid; i < HISTN; i += NT) hist[i] = 0;
    __syncthreads();
    for (int i = tid; i < cnt; i += NT)
        atomicAdd(&hist[score_bin(~(unsigned)(g_keys[b][i] >> 32))], 1);
    __syncthreads();

    // hierarchical suffix scan: base[bb] = # candidates in bins > bb
    int h0 = hist[3 * tid], h1 = hist[3 * tid + 1], h2 = hist[3 * tid + 2];
    int loc = h0 + h1 + h2;
    int v = loc;
#pragma unroll
    for (int o = 1; o < 32; o <<= 1) {
        int u = __shfl_down_sync(0xffffffffu, v, o);
        if (lane + o < 32) v += u;
    }
    if (lane == 0) s_wsum[warp] = v;
    __syncthreads();
    if (warp == 0) {
        int wv = s_wsum[lane];
#pragma unroll
        for (int o = 1; o < 32; o <<= 1) {
            int u = __shfl_down_sync(0xffffffffu, wv, o);
            if (lane + o < 32) wv += u;
        }
        s_wsum[lane] = wv;
    }
    __syncthreads();
    int beyondW = (warp < 31) ? s_wsum[warp + 1] : 0;
    int beyond = v + beyondW - loc;
    base[3 * tid + 2] = beyond;
    base[3 * tid + 1] = beyond + h2;
    base[3 * tid] = beyond + h2 + h1;
    int S_total = s_wsum[0];
    __syncthreads();

    for (int i = tid; i < HISTN; i += NT) hist[i] = 0;
    __syncthreads();
    for (int i = tid; i < cnt; i += NT) {
        ull k = g_keys[b][i];
        int bb = score_bin(~(unsigned)(k >> 32));
        int st = base[bb];
        if (st >= SLOTS) continue;
        int pos = st + atomicAdd(&hist[bb], 1);
        if (pos < SLOTS) tmpk[pos] = k;
    }
    __syncthreads();

    int validcnt = min(S_total, KTOP);
    if (tid == 0) { g_valid[b] = validcnt; g_cnt[b] = 0; }

    float h = (float)hw[b * 2];
    float w = (float)hw[b * 2 + 1];
    float offmul = fmaxf(w, h) + 1.0f;

    // ---- fused exact-rank placement + decode + global write ----
    int S_use = min(S_total, SLOTS);
    for (int i = tid; i < S_use; i += NT) {
        ull key = tmpk[i];
        int bb = score_bin(~(unsigned)(key >> 32));
        int st = base[bb];
        if (st >= KTOP) continue;
        int en = min(st + hist[bb], SLOTS);
        int r = 0;
        for (int j = st; j < en; j++) r += (tmpk[j] < key);
        int pos = st + r;
        if (pos >= KTOP) continue;

        unsigned idx = (unsigned)key;
        int n = (int)(idx / NCLS);
        int c = (int)(idx % NCLS);
        const float* pr = props + ((size_t)b * NPROP + n) * 4;
        float p0 = pr[0], p1 = pr[1], p2 = pr[2], p3 = pr[3];
        float px = (p0 + p2) * 0.5f;
        float py = (p1 + p3) * 0.5f;
        float pw = p2 - p0;
        float ph = p3 - p1;
        const float* dd = reg + ((size_t)b * NPROP + n) * (NCLS * 4) + c * 4;
        float dx = dd[0] * 0.1f;
        float dy = dd[1] * 0.1f;
        float dw = fminf(fmaxf(dd[2] * 0.2f, -MAXR), MAXR);
        float dh = fminf(fmaxf(dd[3] * 0.2f, -MAXR), MAXR);
        float gw = pw * expf(dw);
        float gh = ph * expf(dh);
        float gx = px + pw * dx;
        float gy = py + ph * dy;
        float x1 = fminf(fmaxf(gx - 0.5f * gw, 0.f), w);
        float y1 = fminf(fmaxf(gy - 0.5f * gh, 0.f), h);
        float x2 = fminf(fmaxf(gx + 0.5f * gw, 0.f), w);
        float y2 = fminf(fmaxf(gy + 0.5f * gh, 0.f), h);
        float off = (float)c * offmul;
        g_skey[b][pos] = key;
        g_bout[b][pos] = make_float4(x1, y1, x2, y2);
        g_obox[b][pos] = make_float4(x1 + off, y1 + off, x2 + off, y2 + off);
        g_lab[b][pos] = (uchar)c;
        g_alive[b][pos] = 1;
    }
    // padding
    for (int i = validcnt + tid; i < KTOP; i += NT) {
        g_lab[b][i] = 255;
        g_alive[b][i] = 0;
    }
}

// ---------------- 3: per-class NMS + (last block) output ----------------
// grid = BATCH*10 blocks, 256 threads; block = (b, class-group of 8)
// smem: sb float4 32768 | clist short 4096 | slab 2048 | salive 2048 = 40960
#define SMEM_NMS 40960
extern __shared__ char dynnms[];

__global__ void __launch_bounds__(256) k_nms_out(float* __restrict__ out) {
    int b = blockIdx.x / 10;
    int cg = blockIdx.x % 10;
    int tid = threadIdx.x;
    int lane = tid & 31;
    int warp = tid >> 5;

    float4* sb = (float4*)dynnms;
    short* clist = (short*)(dynnms + 32768);
    uchar* slab = (uchar*)(dynnms + 36864);
    uchar* salive = (uchar*)(dynnms + 38912);
    __shared__ int s_cnt[8], s_base[8];
    __shared__ int s_last;
    __shared__ int s_wsum2[8];
    __shared__ int s_total;

    int valid = g_valid[b];

    for (int i = tid; i < KTOP; i += 256) {
        sb[i] = g_obox[b][i];
        slab[i] = g_lab[b][i];
        salive[i] = g_alive[b][i];
    }
    __syncthreads();

    int c = cg * 8 + warp;
    // count members
    int n2 = 0;
    for (int k0 = 0; k0 < valid; k0 += 32) {
        int i = k0 + lane;
        bool mine = (i < valid) && ((int)slab[i] == c);
        n2 += __popc(__ballot_sync(0xffffffffu, mine));
    }
    if (lane == 0) s_cnt[warp] = n2;
    __syncthreads();
    if (tid == 0) {
        int acc = 0;
        for (int k = 0; k < 8; k++) { s_base[k] = acc; acc += s_cnt[k]; }
    }
    __syncthreads();
    int cb = s_base[warp];

    // compact member indices (sorted order preserved)
    int wr = 0;
    for (int k0 = 0; k0 < valid; k0 += 32) {
        int i = k0 + lane;
        bool mine = (i < valid) && ((int)slab[i] == c);
        unsigned mm = __ballot_sync(0xffffffffu, mine);
        if (mine) clist[cb + wr + __popc(mm & ((1u << lane) - 1))] = (short)i;
        wr += __popc(mm);
    }
    __syncwarp(0xffffffffu);

    // greedy NMS within class
    for (int s2 = 0; s2 < n2; s2++) {
        int is = clist[cb + s2];
        if (!salive[is]) continue;
        float4 A = sb[is];
        float areaA = fmaxf(A.z - A.x, 0.f) * fmaxf(A.w - A.y, 0.f);
        for (int t = s2 + 1 + lane; t < n2; t += 32) {
            int jt = clist[cb + t];
            if (!salive[jt]) continue;
            float4 q = sb[jt];
            float inter = fmaxf(fminf(A.z, q.z) - fmaxf(A.x, q.x), 0.f) *
                          fmaxf(fminf(A.w, q.w) - fmaxf(A.y, q.y), 0.f);
            float areaB = fmaxf(q.z - q.x, 0.f) * fmaxf(q.w - q.y, 0.f);
            float uni = areaA + areaB - inter;
            if (uni > 0.f && inter > IOU_THR * uni) {
                salive[jt] = 0;
                g_alive[b][jt] = 0;
            }
        }
        __syncwarp(0xffffffffu);
    }
    __syncthreads();

    // ---- completion: last block per image emits output ----
    if (tid == 0) {
        __threadfence();
        int old = atomicAdd(&g_done[b], 1);
        s_last = (old == 9);
    }
    __syncthreads();
    if (!s_last) return;
    __threadfence();   // acquire all other blocks' g_alive writes
    if (tid == 0) g_done[b] = 0;

    // prefix over alive flags (8 per thread)
    int a[8], ps = 0;
#pragma unroll
    for (int k = 0; k < 8; k++) { a[k] = g_alive[b][8 * tid + k]; ps += a[k]; }
    int sc = ps;
#pragma unroll
    for (int o = 1; o < 32; o <<= 1) {
        int u = __shfl_up_sync(0xffffffffu, sc, o);
        if (lane >= o) sc += u;
    }
    if (lane == 31) s_wsum2[warp] = sc;
    __syncthreads();
    if (warp == 0 && lane < 8) {
        int wv = s_wsum2[lane];
#pragma unroll
        for (int o = 1; o < 8; o <<= 1) {
            int u = __shfl_up_sync(0x000000ffu, wv, o);
            if (lane >= o) wv += u;
        }
        s_wsum2[lane] = wv;
        if (lane == 7) s_total = wv;
    }
    __syncthreads();
    int wbase = warp ? s_wsum2[warp - 1] : 0;
    int run = wbase + sc - ps;   // exclusive prefix for this thread's first flag

#pragma unroll
    for (int k = 0; k < 8; k++) {
        if (a[k] && run < OUTK) {
            int i = 8 * tid + k;
            ull key = g_skey[b][i];
            ((float4*)out)[b * OUTK + run] = g_bout[b][i];
            out[BATCH * OUTK * 4 + b * OUTK + run] = __uint_as_float(~(unsigned)(key >> 32));
            out[BATCH * OUTK * 5 + b * OUTK + run] = (float)((unsigned)key % NCLS);
        }
        run += a[k];
    }
    int kept = min(s_total, OUTK);
    for (int r = kept + tid; r < OUTK; r += 256) {
        ((float4*)out)[b * OUTK + r] = make_float4(0.f, 0.f, 0.f, 0.f);
        out[BATCH * OUTK * 4 + b * OUTK + r] = 0.0f;
        out[BATCH * OUTK * 5 + b * OUTK + r] = -1.0f;
    }
}

// ---------------- launch ----------------
extern "C" void kernel_launch(void* const* d_in, const int* in_sizes, int n_in,
                              void* d_out, int out_size) {
    const float* cls = (const float*)d_in[0];   // [16,2048,81]
    const float* reg = (const float*)d_in[1];   // [16,2048,320]
    const float* props = (const float*)d_in[2]; // [16,2048,4]
    const int* hw = (const int*)d_in[3];        // [16,2]
    float* out = (float*)d_out;

    cudaFuncSetAttribute(k_select,
                         cudaFuncAttributeMaxDynamicSharedMemorySize, SMEM_SEL);
    cudaFuncSetAttribute(k_nms_out,
                         cudaFuncAttributeMaxDynamicSharedMemorySize, SMEM_NMS);

    k_softmax_compact<<<BATCH * NPROP / 8, 256>>>(cls);
    k_select<<<BATCH, NT, SMEM_SEL>>>(reg, props, hw);
    k_nms_out<<<BATCH * 10, 256, SMEM_NMS>>>(out);
}